// round 12
// baseline (speedup 1.0000x reference)
#include <cuda_runtime.h>
#include <cuda_bf16.h>
#include <cstdint>

// Problem constants
#define NGRAPH 512
#define NPG    125
#define D      128
#define SH     69
#define NC     10

// d_out float offsets
#define P1_OFF  0
#define P2_OFF  1024
#define IND_OFF 2048
#define S_OFF   2560
#define E_OFF   642560
#define Q_OFF   1297920

// ---- smem layout (bytes) ---------------------------------------------------
#define HHI_B   0          // H hi  [128][128] bf16, XOR-swizzled (32768) - live thru E
#define HLO_B   32768      // H lo  (32768) - live thru E
#define WHI_B   65536      // W1^T hi (18432); aliased after stage A
#define WLO_B   83968      // W1^T lo (18432); aliased after stage A
// aliases into the dead W region
#define ZRED_B  65536      // Zred [2][128][11] f32 = 11264
#define STHI_B  76800      // S^T hi [16][128] bf16 swizzled (4096)
#define STLO_B  80896      // S^T lo (4096)
#define ES_B    84992      // Es 1280 f (5120)
#define P1S_B   90112      // 1024 f
#define P2S_B   94208      // 128 f
#define TS_B    94720      // 80 f
#define QR_B    95040      // 160 f
// persistent (16B-aligned where float4-copied)
#define B1S_B   107392     // 72 f (288)
#define W2P_B   107680     // W2 padded [72][12] f32 (3456)
#define RED_B   111136     // 32 f
#define SC_B    111264     // 2 f
#define CORR_B  111272     // 32 f
#define CM_B    111400     // 16 f
#define FMS_B   111464     // 16 f
// small staged params
#define B2S_B   111552     // 12 f
#define PB1S_B  111600     // 8 f
#define PB2S_B  111632     // 16 f
#define CIS_B   111696     // 32 f
#define CIAS_B  111824     // 32 f
#define SMEM_TOTAL 111952  // ~109.3 KB -> 2 CTAs/SM

// ---- precomputed weight images (written by ciflow_prep) --------------------
__device__ __align__(16) uint32_t gW1HI[4608];   // 18432 B swizzled image
__device__ __align__(16) uint32_t gW1LO[4608];
__device__ __align__(16) float    gW2P[864];     // [72][12]
__device__ __align__(16) float    gB1[72];

// ---------------------------------------------------------------------------
__device__ __forceinline__ uint32_t smem_u32(const void* p) {
    uint32_t a;
    asm("{ .reg .u64 t; cvta.to.shared.u64 t, %1; cvt.u32.u64 %0, t; }"
        : "=r"(a) : "l"(p));
    return a;
}
__device__ __forceinline__ void ldsm4(uint32_t a, uint32_t& r0, uint32_t& r1,
                                      uint32_t& r2, uint32_t& r3) {
    asm volatile("ldmatrix.sync.aligned.m8n8.x4.shared.b16 {%0,%1,%2,%3}, [%4];"
                 : "=r"(r0), "=r"(r1), "=r"(r2), "=r"(r3) : "r"(a));
}
__device__ __forceinline__ void ldsm2(uint32_t a, uint32_t& r0, uint32_t& r1) {
    asm volatile("ldmatrix.sync.aligned.m8n8.x2.shared.b16 {%0,%1}, [%2];"
                 : "=r"(r0), "=r"(r1) : "r"(a));
}
__device__ __forceinline__ void ldsm2t(uint32_t a, uint32_t& r0, uint32_t& r1) {
    asm volatile("ldmatrix.sync.aligned.m8n8.x2.trans.shared.b16 {%0,%1}, [%2];"
                 : "=r"(r0), "=r"(r1) : "r"(a));
}
#define MMA(ac, a0, a1, a2, a3, b0, b1) \
    asm volatile("mma.sync.aligned.m16n8k16.row.col.f32.bf16.bf16.f32 " \
                 "{%0,%1,%2,%3}, {%4,%5,%6,%7}, {%8,%9}, {%0,%1,%2,%3};" \
                 : "+f"((ac)[0]), "+f"((ac)[1]), "+f"((ac)[2]), "+f"((ac)[3]) \
                 : "r"(a0), "r"(a1), "r"(a2), "r"(a3), "r"(b0), "r"(b1))

// element (row, bf16-pair p) -> swizzled byte offset (row stride 256B)
__device__ __forceinline__ uint32_t sw_off(int row, int p) {
    return (uint32_t)row * 256u + (uint32_t)(((p >> 2) ^ (row & 7)) << 4)
         + (uint32_t)((p & 3) << 2);
}

// packed f32 pair -> bf16x2 hi + bf16x2 lo (residual), both .rn
__device__ __forceinline__ void split2(float x0, float x1,
                                       uint32_t& hi, uint32_t& lo)
{
    asm("cvt.rn.bf16x2.f32 %0, %1, %2;" : "=r"(hi) : "f"(x1), "f"(x0));
    float r0 = x0 - __uint_as_float(hi << 16);
    float r1 = x1 - __uint_as_float(hi & 0xffff0000u);
    asm("cvt.rn.bf16x2.f32 %0, %1, %2;" : "=r"(lo) : "f"(r1), "f"(r0));
}

// ---------------------------------------------------------------------------
// Threefry-2x32 (JAX partitionable) — bit-exact since R1
// ---------------------------------------------------------------------------
__device__ __forceinline__ void threefry2x32(uint32_t k0, uint32_t k1,
                                             uint32_t c0, uint32_t c1,
                                             uint32_t& y0, uint32_t& y1)
{
    uint32_t ks2 = k0 ^ k1 ^ 0x1BD11BDAu;
    uint32_t x0 = c0 + k0, x1 = c1 + k1;
#define TF_RND(r) { x0 += x1; x1 = (x1 << (r)) | (x1 >> (32 - (r))); x1 ^= x0; }
    TF_RND(13) TF_RND(15) TF_RND(26) TF_RND(6)  x0 += k1;  x1 += ks2 + 1u;
    TF_RND(17) TF_RND(29) TF_RND(16) TF_RND(24) x0 += ks2; x1 += k0  + 2u;
    TF_RND(13) TF_RND(15) TF_RND(26) TF_RND(6)  x0 += k0;  x1 += k1  + 3u;
    TF_RND(17) TF_RND(29) TF_RND(16) TF_RND(24) x0 += k1;  x1 += ks2 + 4u;
    TF_RND(13) TF_RND(15) TF_RND(26) TF_RND(6)  x0 += ks2; x1 += k0  + 5u;
#undef TF_RND
    y0 = x0; y1 = x1;
}
__device__ __forceinline__ float jax_unit_uniform(uint32_t f)
{
    uint32_t y0, y1;
    threefry2x32(0u, 42u, 0u, f, y0, y1);
    uint32_t bits = y0 ^ y1;
    float v = __uint_as_float((bits >> 9) | 0x3f800000u) - 1.0f;
    return (v == 0.0f) ? 1.17549435e-38f : v;
}

// ---------------------------------------------------------------------------
// Pre-kernel: build W1 hi/lo swizzled images + padded W2 + b1 (once per call)
// ---------------------------------------------------------------------------
__global__ void ciflow_prep(const float* __restrict__ w1,
                            const float* __restrict__ w2,
                            const float* __restrict__ b1)
{
    int i = blockIdx.x * 256 + threadIdx.x;   // 0..4607
    int n = i >> 6, p = i & 63;
    float x0 = (n < SH) ? w1[(2 * p)     * SH + n] : 0.0f;
    float x1 = (n < SH) ? w1[(2 * p + 1) * SH + n] : 0.0f;
    uint32_t hi, lo;
    split2(x0, x1, hi, lo);
    uint32_t w = sw_off(n, p) >> 2;
    gW1HI[w] = hi;
    gW1LO[w] = lo;
    if (i < 864) {
        int r = i / 12, c = i - r * 12;
        gW2P[i] = (r < SH && c < NC) ? w2[r * NC + c] : 0.0f;
    }
    if (i < 72) gB1[i] = (i < SH) ? b1[i] : 0.0f;
}

// ---------------------------------------------------------------------------
// Fused kernel: one block per graph, 512 threads, 2 CTAs/SM, HMMA A + E.
// ---------------------------------------------------------------------------
__global__ __launch_bounds__(512, 2) void ciflow_fused(
    const float* __restrict__ H,
    const int*   __restrict__ targets,
    const float* __restrict__ b2,
    const float* __restrict__ wf,  const float* __restrict__ bf,
    const float* __restrict__ p1,  const float* __restrict__ pb1,
    const float* __restrict__ p2,  const float* __restrict__ pb2,
    const float* __restrict__ ci,  const float* __restrict__ cia,
    float* __restrict__ out)
{
    extern __shared__ char smc[];
    const uint32_t sb = smem_u32(smc);

    float* b1s  = (float*)(smc + B1S_B);
    float* W2p  = (float*)(smc + W2P_B);
    float* Zrd  = (float*)(smc + ZRED_B);
    float* b2s  = (float*)(smc + B2S_B);
    float* pb1s = (float*)(smc + PB1S_B);
    float* pb2s = (float*)(smc + PB2S_B);
    float* cis  = (float*)(smc + CIS_B);
    float* cias = (float*)(smc + CIAS_B);

    const int g    = blockIdx.x;
    const int tid  = threadIdx.x;
    const int lane = tid & 31;
    const int wid  = tid >> 5;

    // ---- convert H + copy precomputed W images + stage small params ---------
    const float*  Hg  = H + (size_t)g * NPG * D;
    const float4* Hg4 = (const float4*)Hg;
    for (int i = tid; i < NPG * 32; i += 512) {            // 4000 float4
        int m = i >> 5, q = i & 31;
        float4 v = Hg4[i];
        uint32_t hi0, lo0, hi1, lo1;
        split2(v.x, v.y, hi0, lo0);
        split2(v.z, v.w, hi1, lo1);
        uint32_t o = sw_off(m, 2 * q);
        *(uint2*)(smc + HHI_B + o) = make_uint2(hi0, hi1);
        *(uint2*)(smc + HLO_B + o) = make_uint2(lo0, lo1);
    }
    for (int i = tid; i < 3 * 32; i += 512) {              // zero rows 125..127
        int m = NPG + (i >> 5), q = i & 31;
        uint32_t o = sw_off(m, 2 * q);
        *(uint2*)(smc + HHI_B + o) = make_uint2(0u, 0u);
        *(uint2*)(smc + HLO_B + o) = make_uint2(0u, 0u);
    }
    {
        const float4* s1 = (const float4*)gW1HI;
        const float4* s2 = (const float4*)gW1LO;
        float4* d1 = (float4*)(smc + WHI_B);
        float4* d2 = (float4*)(smc + WLO_B);
        for (int i = tid; i < 1152; i += 512) { d1[i] = s1[i]; d2[i] = s2[i]; }
        const float4* s3 = (const float4*)gW2P;
        float4* d3 = (float4*)(smc + W2P_B);
        for (int i = tid; i < 216; i += 512) d3[i] = s3[i];
        if (tid < 18) ((float4*)b1s)[tid] = ((const float4*)gB1)[tid];
    }
    if (wid == 15) {                                       // small tail params
        if (lane < 10) b2s[lane]  = __ldg(&b2[lane]);
        if (lane < 8)  pb1s[lane] = __ldg(&pb1[lane]);
        if (lane < 16) pb2s[lane] = __ldg(&pb2[lane]);
        cis[lane]  = __ldg(&ci[lane]);
        cias[lane] = __ldg(&cia[lane]);
    }
    __syncthreads();

    // ---- stage A via mma.sync: A = H @ W1t^T, 3-term bf16 compensation -----
    const int mtile = wid >> 1;
    const int half  = wid & 1;
    const int tA = lane >> 3, rA = lane & 7;
    const int mRow = mtile * 16 + ((tA & 1) << 3) + rA;
    const uint32_t aBase = sb + HHI_B + (uint32_t)mRow * 256u;
    const int aSw = mRow & 7, aCo = tA >> 1;
    const int nR4 = ((tA >> 1) << 3) + rA;
    const uint32_t b4Base = sb + WHI_B + (uint32_t)nR4 * 256u;
    const int b4Sw = rA, b4Co = tA & 1;
    const int t2 = (lane >> 3) & 1;
    const uint32_t b2Base = sb + WHI_B + (uint32_t)rA * 256u;
    const int b2Co = t2;

    float acc[5][4];
#pragma unroll
    for (int t = 0; t < 5; ++t)
#pragma unroll
        for (int c = 0; c < 4; ++c) acc[t][c] = 0.0f;

#pragma unroll 2
    for (int s = 0; s < 8; ++s) {
        const int c2 = 2 * s;
        uint32_t ah0, ah1, ah2, ah3, al0, al1, al2, al3;
        uint32_t aAddr = aBase + (uint32_t)(((c2 + aCo) ^ aSw) << 4);
        ldsm4(aAddr,         ah0, ah1, ah2, ah3);
        ldsm4(aAddr + 32768, al0, al1, al2, al3);

        if (half == 0) {
            uint32_t bh0, bh1, bh2, bh3, bl0, bl1, bl2, bl3;
            uint32_t bA = b4Base + (uint32_t)(((c2 + b4Co) ^ b4Sw) << 4);
            ldsm4(bA,         bh0, bh1, bh2, bh3);          // tiles 0,1
            ldsm4(bA + 18432, bl0, bl1, bl2, bl3);
            MMA(acc[0], ah0, ah1, ah2, ah3, bh0, bh1);
            MMA(acc[0], ah0, ah1, ah2, ah3, bl0, bl1);
            MMA(acc[0], al0, al1, al2, al3, bh0, bh1);
            MMA(acc[1], ah0, ah1, ah2, ah3, bh2, bh3);
            MMA(acc[1], ah0, ah1, ah2, ah3, bl2, bl3);
            MMA(acc[1], al0, al1, al2, al3, bh2, bh3);
            bA += 2u * 2048u;                               // tiles 2,3
            ldsm4(bA,         bh0, bh1, bh2, bh3);
            ldsm4(bA + 18432, bl0, bl1, bl2, bl3);
            MMA(acc[2], ah0, ah1, ah2, ah3, bh0, bh1);
            MMA(acc[2], ah0, ah1, ah2, ah3, bl0, bl1);
            MMA(acc[2], al0, al1, al2, al3, bh0, bh1);
            MMA(acc[3], ah0, ah1, ah2, ah3, bh2, bh3);
            MMA(acc[3], ah0, ah1, ah2, ah3, bl2, bl3);
            MMA(acc[3], al0, al1, al2, al3, bh2, bh3);
            uint32_t bB = b2Base + 4u * 2048u
                        + (uint32_t)(((c2 + b2Co) ^ rA) << 4);   // tile 4
            ldsm2(bB,         bh0, bh1);
            ldsm2(bB + 18432, bl0, bl1);
            MMA(acc[4], ah0, ah1, ah2, ah3, bh0, bh1);
            MMA(acc[4], ah0, ah1, ah2, ah3, bl0, bl1);
            MMA(acc[4], al0, al1, al2, al3, bh0, bh1);
        } else {
            uint32_t bh0, bh1, bh2, bh3, bl0, bl1, bl2, bl3;
            uint32_t bA = b4Base + 5u * 2048u
                        + (uint32_t)(((c2 + b4Co) ^ b4Sw) << 4); // tiles 5,6
            ldsm4(bA,         bh0, bh1, bh2, bh3);
            ldsm4(bA + 18432, bl0, bl1, bl2, bl3);
            MMA(acc[0], ah0, ah1, ah2, ah3, bh0, bh1);
            MMA(acc[0], ah0, ah1, ah2, ah3, bl0, bl1);
            MMA(acc[0], al0, al1, al2, al3, bh0, bh1);
            MMA(acc[1], ah0, ah1, ah2, ah3, bh2, bh3);
            MMA(acc[1], ah0, ah1, ah2, ah3, bl2, bl3);
            MMA(acc[1], al0, al1, al2, al3, bh2, bh3);
            bA += 2u * 2048u;                                // tiles 7,8
            ldsm4(bA,         bh0, bh1, bh2, bh3);
            ldsm4(bA + 18432, bl0, bl1, bl2, bl3);
            MMA(acc[2], ah0, ah1, ah2, ah3, bh0, bh1);
            MMA(acc[2], ah0, ah1, ah2, ah3, bl0, bl1);
            MMA(acc[2], al0, al1, al2, al3, bh0, bh1);
            MMA(acc[3], ah0, ah1, ah2, ah3, bh2, bh3);
            MMA(acc[3], ah0, ah1, ah2, ah3, bl2, bl3);
            MMA(acc[3], al0, al1, al2, al3, bh2, bh3);
        }
    }

    // ---- register epilogue: relu + b1, partial Z = A @ W2 -------------------
    const int nOff = 2 * (lane & 3);
    const int r0   = mtile * 16 + (lane >> 2);
    const int ntB  = half ? 5 : 0;
    const int ntC  = half ? 4 : 5;
    float z0[10], z1[10];
#pragma unroll
    for (int c = 0; c < 10; ++c) { z0[c] = 0.f; z1[c] = 0.f; }
#pragma unroll
    for (int ti = 0; ti < 5; ++ti) {
        if (ti < ntC) {
            int n = (ntB + ti) * 8 + nOff;
            float a00 = fmaxf(acc[ti][0] + b1s[n],     0.0f);
            float a01 = fmaxf(acc[ti][1] + b1s[n + 1], 0.0f);
            float a10 = fmaxf(acc[ti][2] + b1s[n],     0.0f);
            float a11 = fmaxf(acc[ti][3] + b1s[n + 1], 0.0f);
            const float* w2r0 = W2p + n * 12;
            const float* w2r1 = w2r0 + 12;
#pragma unroll
            for (int c = 0; c < 10; ++c) {
                float wa = w2r0[c], wb = w2r1[c];
                z0[c] = fmaf(a00, wa, fmaf(a01, wb, z0[c]));
                z1[c] = fmaf(a10, wa, fmaf(a11, wb, z1[c]));
            }
        }
    }
#pragma unroll
    for (int off = 1; off <= 2; off <<= 1) {
#pragma unroll
        for (int c = 0; c < 10; ++c) {
            z0[c] += __shfl_xor_sync(0xffffffffu, z0[c], off);
            z1[c] += __shfl_xor_sync(0xffffffffu, z1[c], off);
        }
    }
    __syncthreads();           // all ldmatrix reads of W region done
    if ((lane & 3) == 0) {
#pragma unroll
        for (int c = 0; c < 10; ++c) {
            Zrd[(half * 128 + r0) * 11 + c]     = z0[c];
            Zrd[(half * 128 + r0 + 8) * 11 + c] = z1[c];
        }
    }
    __syncthreads();

    // ---- Z combine + softmax -> S gmem + S^T bf16 hi/lo; others prefetch ---
    float* p1s = (float*)(smc + P1S_B);
    float* p2s = (float*)(smc + P2S_B);
    if (tid < 128) {
        int m = tid;
        const uint32_t mChunk = (uint32_t)((m >> 3) << 4);
        const uint32_t mRem   = (uint32_t)(((m >> 1) & 3) << 2)
                              + (uint32_t)((m & 1) << 1);
        if (m < NPG) {
            float z[10];
#pragma unroll
            for (int c = 0; c < 10; ++c)
                z[c] = Zrd[m * 11 + c] + Zrd[(128 + m) * 11 + c] + b2s[c];
            float mx = z[0];
#pragma unroll
            for (int c = 1; c < 10; ++c) mx = fmaxf(mx, z[c]);
            float ssum = 0.0f;
#pragma unroll
            for (int c = 0; c < 10; ++c) { z[c] = expf(z[c] - mx); ssum += z[c]; }
            float inv = 1.0f / ssum;
            float* gout = out + S_OFF + ((size_t)g * NPG + m) * NC;
#pragma unroll
            for (int c = 0; c < 10; ++c) z[c] *= inv;
#pragma unroll
            for (int c = 0; c < 5; ++c)
                *(float2*)(gout + 2 * c) = make_float2(z[2 * c], z[2 * c + 1]);
#pragma unroll
            for (int c = 0; c < 10; ++c) {
                __nv_bfloat16 shi = __float2bfloat16(z[c]);
                __nv_bfloat16 slo = __float2bfloat16(z[c] - __bfloat162float(shi));
                uint32_t off = (uint32_t)c * 256u
                             + ((mChunk ^ (uint32_t)((c & 7) << 4))) + mRem;
                *(unsigned short*)(smc + STHI_B + off) = __bfloat16_as_ushort(shi);
                *(unsigned short*)(smc + STLO_B + off) = __bfloat16_as_ushort(slo);
            }
        } else {
            // m = 125..127: zero K-pad columns of S^T (all 16 rows)
#pragma unroll
            for (int c = 0; c < 16; ++c) {
                uint32_t off = (uint32_t)c * 256u
                             + ((mChunk ^ (uint32_t)((c & 7) << 4))) + mRem;
                *(unsigned short*)(smc + STHI_B + off) = 0;
                *(unsigned short*)(smc + STLO_B + off) = 0;
            }
        }
    } else {
        int t = tid - 128;
        for (int i = t; i < 1024; i += 384) p1s[i] = __ldg(&p1[i]);
        if (t < 128) p2s[t] = __ldg(&p2[t]);
    }
    __syncthreads();

    // ---- stage E via mma: E = S^T @ H; pred1 fused into epilogue ------------
    float* Es  = (float*)(smc + ES_B);
    float* red = (float*)(smc + RED_B);
    {
        const int aRow = ((tA & 1) << 3) + rA;
        const uint32_t aHiBase = sb + STHI_B + (uint32_t)aRow * 256u;
        const int aXor = aRow & 7;
        const int bOff = lane & 15;                    // H row within k-step
        uint32_t bAddr = sb + HHI_B + (uint32_t)bOff * 256u
                       + (uint32_t)((wid ^ (bOff & 7)) << 4);

        float e[4] = {0.f, 0.f, 0.f, 0.f};
#pragma unroll
        for (int s = 0; s < 8; ++s) {
            uint32_t aAddr = aHiBase + (uint32_t)(((2 * s + aCo) ^ aXor) << 4);
            uint32_t sh0, sh1, sh2, sh3, sl0, sl1, sl2, sl3;
            ldsm4(aAddr,        sh0, sh1, sh2, sh3);
            ldsm4(aAddr + 4096, sl0, sl1, sl2, sl3);   // STLO = STHI + 4096
            uint32_t bh0, bh1, bl0, bl1;
            ldsm2t(bAddr,         bh0, bh1);
            ldsm2t(bAddr + 32768, bl0, bl1);           // HLO
            MMA(e, sh0, sh1, sh2, sh3, bh0, bh1);
            MMA(e, sh0, sh1, sh2, sh3, bl0, bl1);
            MMA(e, sl0, sl1, sl2, sl3, bh0, bh1);
            bAddr += 16u * 256u;
        }
        const int c = lane >> 2;
        const int d = 8 * wid + 2 * (lane & 3);
        float* Eout = out + E_OFF + (size_t)g * (NC * D);
        *(float2*)(Es + c * D + d)   = make_float2(e[0], e[1]);
        *(float2*)(Eout + c * D + d) = make_float2(e[0], e[1]);
        if (c + 8 < NC) {
            *(float2*)(Es + (c + 8) * D + d)   = make_float2(e[2], e[3]);
            *(float2*)(Eout + (c + 8) * D + d) = make_float2(e[2], e[3]);
        }

        // fused pred1 partials from fragments
        const int i0 = c * D + d;
        float2 w0 = __ldg((const float2*)(wf + 2 * i0));
        float2 w1 = __ldg((const float2*)(wf + 2 * (i0 + 1)));
        float s0 = e[0] * w0.x + e[1] * w1.x;
        float s1 = e[0] * w0.y + e[1] * w1.y;
        if (c + 8 < NC) {
            const int i2 = (c + 8) * D + d;
            float2 w2v = __ldg((const float2*)(wf + 2 * i2));
            float2 w3v = __ldg((const float2*)(wf + 2 * (i2 + 1)));
            s0 = fmaf(e[2], w2v.x, fmaf(e[3], w3v.x, s0));
            s1 = fmaf(e[2], w2v.y, fmaf(e[3], w3v.y, s1));
        }
#pragma unroll
        for (int off = 16; off; off >>= 1) {
            s0 += __shfl_down_sync(0xffffffffu, s0, off);
            s1 += __shfl_down_sync(0xffffffffu, s1, off);
        }
        if (lane == 0) { red[wid * 2] = s0; red[wid * 2 + 1] = s1; }
    }
    __syncthreads();

    // ======================= fused downstream ================================
    float* ts    = (float*)(smc + TS_B);
    float* qraw  = (float*)(smc + QR_B);
    float* fms   = (float*)(smc + FMS_B);
    float* sc    = (float*)(smc + SC_B);
    float* corrs = (float*)(smc + CORR_B);
    float* cmask = (float*)(smc + CM_B);

    // epoch 2: sampling | correlation | Q hidden
    if (tid == 0) {
        float z0v = bf[0], z1v = bf[1];
#pragma unroll
        for (int w = 0; w < 16; ++w) { z0v += red[2 * w]; z1v += red[2 * w + 1]; }
        out[P1_OFF + g * 2 + 0] = z0v;
        out[P1_OFF + g * 2 + 1] = z1v;
        float mx = fmaxf(z0v, z1v);
        float e0 = expf(z0v - mx), e1 = expf(z1v - mx);
        float inv = 1.0f / (e0 + e1);
        float pp0 = e0 * inv, pp1 = e1 * inv;

        float u0 = jax_unit_uniform(2u * g);
        float u1 = jax_unit_uniform(2u * g + 1u);
        float l0 = logf(pp0 + 1e-12f) - logf(-logf(u0));
        float l1 = logf(pp1 + 1e-12f) - logf(-logf(u1));
        int sample = (l1 > l0) ? 1 : 0;

        out[IND_OFF + g] = (sample == targets[g]) ? 1.0f : 0.0f;
        sc[0] = pp0 + ((sample == 0) ? (1.0f - pp0) : -pp0);
        sc[1] = pp1 + ((sample == 1) ? (1.0f - pp1) : -pp1);
    }

    if (tid >= 32 && tid < 64) {
        int t = tid - 32;
        int c = t >> 4, f = t & 15;
        float a0 = cis[f], a1 = cis[16 + f];
        float m = fmaxf(a0, a1);
        float e0 = expf(a0 - m), e1 = expf(a1 - m);
        float colv = ((c == 0) ? e0 : e1) / (e0 + e1);
        float rm = -1e30f;
        for (int ff = 0; ff < 16; ++ff) rm = fmaxf(rm, cias[c * 16 + ff]);
        float rs = 0.f;
        for (int ff = 0; ff < 16; ++ff) rs += expf(cias[c * 16 + ff] - rm);
        corrs[c * 16 + f] = colv * (expf(cias[c * 16 + f] - rm) / rs);
    }

    if (tid >= 192) {                // Q hidden, 4-way k-split
        int t  = tid - 192;
        int u  = t >> 2, ks = t & 3;
        int c  = u >> 3, j = u & 7;
        float a = 0.0f;
        const float* ec = Es + c * 128 + 32 * ks;
        const float* pj = p1s + (32 * ks) * 8 + j;
#pragma unroll 8
        for (int k = 0; k < 32; ++k) a = fmaf(ec[k], pj[8 * k], a);
        a += __shfl_down_sync(0xffffffffu, a, 2);
        a += __shfl_down_sync(0xffffffffu, a, 1);
        if (ks == 0) ts[u] = fmaxf(a + pb1s[j], 0.0f);
    }
    __syncthreads();

    // epoch 3: cmask | Q output
    if (tid < 16) cmask[tid] = sc[0] * corrs[tid] + sc[1] * corrs[16 + tid];

    if (tid >= 160 && tid < 320) {
        int t = tid - 160;
        int c = t >> 4, f = t & 15;
        float a = pb2s[f];
#pragma unroll
        for (int j = 0; j < 8; ++j) a = fmaf(ts[c * 8 + j], p2s[j * 16 + f], a);
        qraw[t] = a;
    }
    __syncthreads();

    // epoch 4: Q softmax + feature mask
    if (tid < 160) {
        int c = tid >> 4, f = tid & 15;
        float v = qraw[tid];
        float mx = v;
#pragma unroll
        for (int off = 8; off; off >>= 1)
            mx = fmaxf(mx, __shfl_xor_sync(0xffffffffu, mx, off));
        float e = expf(v - mx);
        float ssum = e;
#pragma unroll
        for (int off = 8; off; off >>= 1)
            ssum += __shfl_xor_sync(0xffffffffu, ssum, off);
        float q = e / ssum;
        out[Q_OFF + (size_t)g * 160 + c * 16 + f] = q;
        float fm = q * cmask[f];
#pragma unroll
        for (int off = 8; off; off >>= 1)
            fm += __shfl_xor_sync(0xffffffffu, fm, off);
        if (f == 0) fms[c] = fm;
    }
    __syncthreads();

    // epoch 5: pred2
    float s0 = 0.f, s1 = 0.f;
#pragma unroll
    for (int r = 0; r < 3; ++r) {
        int i = tid + 512 * r;
        if (i < 1280) {
            float e = fms[i >> 7] * Es[i];
            float2 w = __ldg((const float2*)(wf + 2 * i));
            s0 = fmaf(e, w.x, s0);
            s1 = fmaf(e, w.y, s1);
        }
    }
#pragma unroll
    for (int off = 16; off; off >>= 1) {
        s0 += __shfl_down_sync(0xffffffffu, s0, off);
        s1 += __shfl_down_sync(0xffffffffu, s1, off);
    }
    if (lane == 0) { red[wid * 2] = s0; red[wid * 2 + 1] = s1; }
    __syncthreads();
    if (tid == 0) {
        float z0v = bf[0], z1v = bf[1];
#pragma unroll
        for (int w = 0; w < 16; ++w) { z0v += red[2 * w]; z1v += red[2 * w + 1]; }
        out[P2_OFF + g * 2 + 0] = z0v;
        out[P2_OFF + g * 2 + 1] = z1v;
    }
}

// ---------------------------------------------------------------------------
extern "C" void kernel_launch(void* const* d_in, const int* in_sizes, int n_in,
                              void* d_out, int out_size)
{
    const float* H   = (const float*)d_in[0];
    const int*   tgt = (const int*)  d_in[2];
    const float* w1  = (const float*)d_in[3];
    const float* b1  = (const float*)d_in[4];
    const float* w2  = (const float*)d_in[5];
    const float* b2  = (const float*)d_in[6];
    const float* wf  = (const float*)d_in[7];
    const float* bf  = (const float*)d_in[8];
    const float* p1  = (const float*)d_in[9];
    const float* pb1 = (const float*)d_in[10];
    const float* p2  = (const float*)d_in[11];
    const float* pb2 = (const float*)d_in[12];
    const float* ci  = (const float*)d_in[13];
    const float* cia = (const float*)d_in[14];
    float* out = (float*)d_out;

    static bool attr_set = false;
    if (!attr_set) {
        cudaFuncSetAttribute(ciflow_fused,
                             cudaFuncAttributeMaxDynamicSharedMemorySize, SMEM_TOTAL);
        attr_set = true;
    }

    ciflow_prep<<<18, 256>>>(w1, w2, b1);
    ciflow_fused<<<NGRAPH, 512, SMEM_TOTAL>>>(H, tgt, b2, wf, bf,
                                              p1, pb1, p2, pb2, ci, cia, out);
}

// round 13
// speedup vs baseline: 1.0410x; 1.0410x over previous
#include <cuda_runtime.h>
#include <cuda_bf16.h>
#include <cstdint>

// Problem constants
#define NGRAPH 512
#define NPG    125
#define D      128
#define SH     69
#define NC     10

// d_out float offsets
#define P1_OFF  0
#define P2_OFF  1024
#define IND_OFF 2048
#define S_OFF   2560
#define E_OFF   642560
#define Q_OFF   1297920

// ---- smem layout (bytes) ---------------------------------------------------
#define HHI_B   0          // H hi  [128][128] bf16, XOR-swizzled (32768) - live thru E
#define HLO_B   32768      // H lo  (32768) - live thru E
#define WHI_B   65536      // W1^T hi (18432); aliased after stage A
#define WLO_B   83968      // W1^T lo (18432); aliased after stage A
// aliases into the dead W region
#define ZRED_B  65536      // Zred [2][128][11] f32 = 11264
#define STHI_B  76800      // S^T hi [16][128] bf16 swizzled (4096)
#define STLO_B  80896      // S^T lo (4096)
#define ES_B    84992      // Es 1280 f (5120)
#define P1S_B   90112      // 1024 f
#define P2S_B   94208      // 128 f
#define TS_B    94720      // 80 f
#define QR_B    95040      // 160 f
// persistent (16B-aligned where float4-copied)
#define B1S_B   107392     // 72 f (288)
#define W2P_B   107680     // W2 padded [72][12] f32 (3456)
#define RED_B   111136     // 32 f
#define SC_B    111264     // 2 f
#define CORR_B  111272     // 32 f
#define CM_B    111400     // 16 f
#define FMS_B   111464     // 16 f
// small staged params
#define B2S_B   111552     // 12 f
#define PB1S_B  111600     // 8 f
#define PB2S_B  111632     // 16 f
#define CIS_B   111696     // 32 f
#define CIAS_B  111824     // 32 f
#define SMEM_TOTAL 111952  // ~109.3 KB -> 2 CTAs/SM

// ---- precomputed weight images (written by ciflow_prep) --------------------
__device__ __align__(16) uint32_t gW1HI[4608];   // 18432 B swizzled image
__device__ __align__(16) uint32_t gW1LO[4608];
__device__ __align__(16) float    gW2P[864];     // [72][12]
__device__ __align__(16) float    gB1[72];

// ---------------------------------------------------------------------------
__device__ __forceinline__ uint32_t smem_u32(const void* p) {
    uint32_t a;
    asm("{ .reg .u64 t; cvta.to.shared.u64 t, %1; cvt.u32.u64 %0, t; }"
        : "=r"(a) : "l"(p));
    return a;
}
__device__ __forceinline__ void ldsm4(uint32_t a, uint32_t& r0, uint32_t& r1,
                                      uint32_t& r2, uint32_t& r3) {
    asm volatile("ldmatrix.sync.aligned.m8n8.x4.shared.b16 {%0,%1,%2,%3}, [%4];"
                 : "=r"(r0), "=r"(r1), "=r"(r2), "=r"(r3) : "r"(a));
}
__device__ __forceinline__ void ldsm2(uint32_t a, uint32_t& r0, uint32_t& r1) {
    asm volatile("ldmatrix.sync.aligned.m8n8.x2.shared.b16 {%0,%1}, [%2];"
                 : "=r"(r0), "=r"(r1) : "r"(a));
}
__device__ __forceinline__ void ldsm2t(uint32_t a, uint32_t& r0, uint32_t& r1) {
    asm volatile("ldmatrix.sync.aligned.m8n8.x2.trans.shared.b16 {%0,%1}, [%2];"
                 : "=r"(r0), "=r"(r1) : "r"(a));
}
#define MMA(ac, a0, a1, a2, a3, b0, b1) \
    asm volatile("mma.sync.aligned.m16n8k16.row.col.f32.bf16.bf16.f32 " \
                 "{%0,%1,%2,%3}, {%4,%5,%6,%7}, {%8,%9}, {%0,%1,%2,%3};" \
                 : "+f"((ac)[0]), "+f"((ac)[1]), "+f"((ac)[2]), "+f"((ac)[3]) \
                 : "r"(a0), "r"(a1), "r"(a2), "r"(a3), "r"(b0), "r"(b1))

// element (row, bf16-pair p) -> swizzled byte offset (row stride 256B)
__device__ __forceinline__ uint32_t sw_off(int row, int p) {
    return (uint32_t)row * 256u + (uint32_t)(((p >> 2) ^ (row & 7)) << 4)
         + (uint32_t)((p & 3) << 2);
}

// packed f32 pair -> bf16x2 hi + bf16x2 lo (residual), both .rn
__device__ __forceinline__ void split2(float x0, float x1,
                                       uint32_t& hi, uint32_t& lo)
{
    asm("cvt.rn.bf16x2.f32 %0, %1, %2;" : "=r"(hi) : "f"(x1), "f"(x0));
    float r0 = x0 - __uint_as_float(hi << 16);
    float r1 = x1 - __uint_as_float(hi & 0xffff0000u);
    asm("cvt.rn.bf16x2.f32 %0, %1, %2;" : "=r"(lo) : "f"(r1), "f"(r0));
}

// ---------------------------------------------------------------------------
// Threefry-2x32 (JAX partitionable) — bit-exact since R1
// ---------------------------------------------------------------------------
__device__ __forceinline__ void threefry2x32(uint32_t k0, uint32_t k1,
                                             uint32_t c0, uint32_t c1,
                                             uint32_t& y0, uint32_t& y1)
{
    uint32_t ks2 = k0 ^ k1 ^ 0x1BD11BDAu;
    uint32_t x0 = c0 + k0, x1 = c1 + k1;
#define TF_RND(r) { x0 += x1; x1 = (x1 << (r)) | (x1 >> (32 - (r))); x1 ^= x0; }
    TF_RND(13) TF_RND(15) TF_RND(26) TF_RND(6)  x0 += k1;  x1 += ks2 + 1u;
    TF_RND(17) TF_RND(29) TF_RND(16) TF_RND(24) x0 += ks2; x1 += k0  + 2u;
    TF_RND(13) TF_RND(15) TF_RND(26) TF_RND(6)  x0 += k0;  x1 += k1  + 3u;
    TF_RND(17) TF_RND(29) TF_RND(16) TF_RND(24) x0 += k1;  x1 += ks2 + 4u;
    TF_RND(13) TF_RND(15) TF_RND(26) TF_RND(6)  x0 += ks2; x1 += k0  + 5u;
#undef TF_RND
    y0 = x0; y1 = x1;
}
__device__ __forceinline__ float jax_unit_uniform(uint32_t f)
{
    uint32_t y0, y1;
    threefry2x32(0u, 42u, 0u, f, y0, y1);
    uint32_t bits = y0 ^ y1;
    float v = __uint_as_float((bits >> 9) | 0x3f800000u) - 1.0f;
    return (v == 0.0f) ? 1.17549435e-38f : v;
}

// ---------------------------------------------------------------------------
// Pre-kernel: build W1 hi/lo swizzled images + padded W2 + b1 (once per call)
// ---------------------------------------------------------------------------
__global__ void ciflow_prep(const float* __restrict__ w1,
                            const float* __restrict__ w2,
                            const float* __restrict__ b1)
{
    int i = blockIdx.x * 256 + threadIdx.x;   // 0..4607
    int n = i >> 6, p = i & 63;
    float x0 = (n < SH) ? w1[(2 * p)     * SH + n] : 0.0f;
    float x1 = (n < SH) ? w1[(2 * p + 1) * SH + n] : 0.0f;
    uint32_t hi, lo;
    split2(x0, x1, hi, lo);
    uint32_t w = sw_off(n, p) >> 2;
    gW1HI[w] = hi;
    gW1LO[w] = lo;
    if (i < 864) {
        int r = i / 12, c = i - r * 12;
        gW2P[i] = (r < SH && c < NC) ? w2[r * NC + c] : 0.0f;
    }
    if (i < 72) gB1[i] = (i < SH) ? b1[i] : 0.0f;
}

// ---------------------------------------------------------------------------
// Fused kernel: one block per graph, 512 threads, 2 CTAs/SM, HMMA A + E.
// ---------------------------------------------------------------------------
__global__ __launch_bounds__(512, 2) void ciflow_fused(
    const float* __restrict__ H,
    const int*   __restrict__ targets,
    const float* __restrict__ b2,
    const float* __restrict__ wf,  const float* __restrict__ bf,
    const float* __restrict__ p1,  const float* __restrict__ pb1,
    const float* __restrict__ p2,  const float* __restrict__ pb2,
    const float* __restrict__ ci,  const float* __restrict__ cia,
    float* __restrict__ out)
{
    extern __shared__ char smc[];
    const uint32_t sb = smem_u32(smc);

    float* b1s  = (float*)(smc + B1S_B);
    float* W2p  = (float*)(smc + W2P_B);
    float* Zrd  = (float*)(smc + ZRED_B);
    float* b2s  = (float*)(smc + B2S_B);
    float* pb1s = (float*)(smc + PB1S_B);
    float* pb2s = (float*)(smc + PB2S_B);
    float* cis  = (float*)(smc + CIS_B);
    float* cias = (float*)(smc + CIAS_B);

    const int g    = blockIdx.x;
    const int tid  = threadIdx.x;
    const int lane = tid & 31;
    const int wid  = tid >> 5;

    // ---- convert H + copy precomputed W images + stage small params ---------
    const float*  Hg  = H + (size_t)g * NPG * D;
    const float4* Hg4 = (const float4*)Hg;
    for (int i = tid; i < NPG * 32; i += 512) {            // 4000 float4
        int m = i >> 5, q = i & 31;
        float4 v = Hg4[i];
        uint32_t hi0, lo0, hi1, lo1;
        split2(v.x, v.y, hi0, lo0);
        split2(v.z, v.w, hi1, lo1);
        uint32_t o = sw_off(m, 2 * q);
        *(uint2*)(smc + HHI_B + o) = make_uint2(hi0, hi1);
        *(uint2*)(smc + HLO_B + o) = make_uint2(lo0, lo1);
    }
    for (int i = tid; i < 3 * 32; i += 512) {              // zero rows 125..127
        int m = NPG + (i >> 5), q = i & 31;
        uint32_t o = sw_off(m, 2 * q);
        *(uint2*)(smc + HHI_B + o) = make_uint2(0u, 0u);
        *(uint2*)(smc + HLO_B + o) = make_uint2(0u, 0u);
    }
    {
        const float4* s1 = (const float4*)gW1HI;
        const float4* s2 = (const float4*)gW1LO;
        float4* d1 = (float4*)(smc + WHI_B);
        float4* d2 = (float4*)(smc + WLO_B);
        for (int i = tid; i < 1152; i += 512) { d1[i] = s1[i]; d2[i] = s2[i]; }
        const float4* s3 = (const float4*)gW2P;
        float4* d3 = (float4*)(smc + W2P_B);
        for (int i = tid; i < 216; i += 512) d3[i] = s3[i];
        if (tid < 18) ((float4*)b1s)[tid] = ((const float4*)gB1)[tid];
    }
    if (wid == 15) {                                       // small tail params
        if (lane < 10) b2s[lane]  = __ldg(&b2[lane]);
        if (lane < 8)  pb1s[lane] = __ldg(&pb1[lane]);
        if (lane < 16) pb2s[lane] = __ldg(&pb2[lane]);
        cis[lane]  = __ldg(&ci[lane]);
        cias[lane] = __ldg(&cia[lane]);
    }
    __syncthreads();

    // ---- stage A via mma.sync: A = H @ W1t^T, 3-term bf16 compensation -----
    const int mtile = wid >> 1;
    const int half  = wid & 1;
    const int tA = lane >> 3, rA = lane & 7;
    const int mRow = mtile * 16 + ((tA & 1) << 3) + rA;
    const uint32_t aBase = sb + HHI_B + (uint32_t)mRow * 256u;
    const int aSw = mRow & 7, aCo = tA >> 1;
    const int nR4 = ((tA >> 1) << 3) + rA;
    const uint32_t b4Base = sb + WHI_B + (uint32_t)nR4 * 256u;
    const int b4Sw = rA, b4Co = tA & 1;
    const int t2 = (lane >> 3) & 1;
    const uint32_t b2Base = sb + WHI_B + (uint32_t)rA * 256u;
    const int b2Co = t2;

    float acc[5][4];
#pragma unroll
    for (int t = 0; t < 5; ++t)
#pragma unroll
        for (int c = 0; c < 4; ++c) acc[t][c] = 0.0f;

#pragma unroll 2
    for (int s = 0; s < 8; ++s) {
        const int c2 = 2 * s;
        uint32_t ah0, ah1, ah2, ah3, al0, al1, al2, al3;
        uint32_t aAddr = aBase + (uint32_t)(((c2 + aCo) ^ aSw) << 4);
        ldsm4(aAddr,         ah0, ah1, ah2, ah3);
        ldsm4(aAddr + 32768, al0, al1, al2, al3);

        if (half == 0) {
            uint32_t bh0, bh1, bh2, bh3, bl0, bl1, bl2, bl3;
            uint32_t bA = b4Base + (uint32_t)(((c2 + b4Co) ^ b4Sw) << 4);
            ldsm4(bA,         bh0, bh1, bh2, bh3);          // tiles 0,1
            ldsm4(bA + 18432, bl0, bl1, bl2, bl3);
            MMA(acc[0], ah0, ah1, ah2, ah3, bh0, bh1);
            MMA(acc[0], ah0, ah1, ah2, ah3, bl0, bl1);
            MMA(acc[0], al0, al1, al2, al3, bh0, bh1);
            MMA(acc[1], ah0, ah1, ah2, ah3, bh2, bh3);
            MMA(acc[1], ah0, ah1, ah2, ah3, bl2, bl3);
            MMA(acc[1], al0, al1, al2, al3, bh2, bh3);
            bA += 2u * 2048u;                               // tiles 2,3
            ldsm4(bA,         bh0, bh1, bh2, bh3);
            ldsm4(bA + 18432, bl0, bl1, bl2, bl3);
            MMA(acc[2], ah0, ah1, ah2, ah3, bh0, bh1);
            MMA(acc[2], ah0, ah1, ah2, ah3, bl0, bl1);
            MMA(acc[2], al0, al1, al2, al3, bh0, bh1);
            MMA(acc[3], ah0, ah1, ah2, ah3, bh2, bh3);
            MMA(acc[3], ah0, ah1, ah2, ah3, bl2, bl3);
            MMA(acc[3], al0, al1, al2, al3, bh2, bh3);
            uint32_t bB = b2Base + 4u * 2048u
                        + (uint32_t)(((c2 + b2Co) ^ rA) << 4);   // tile 4
            ldsm2(bB,         bh0, bh1);
            ldsm2(bB + 18432, bl0, bl1);
            MMA(acc[4], ah0, ah1, ah2, ah3, bh0, bh1);
            MMA(acc[4], ah0, ah1, ah2, ah3, bl0, bl1);
            MMA(acc[4], al0, al1, al2, al3, bh0, bh1);
        } else {
            uint32_t bh0, bh1, bh2, bh3, bl0, bl1, bl2, bl3;
            uint32_t bA = b4Base + 5u * 2048u
                        + (uint32_t)(((c2 + b4Co) ^ b4Sw) << 4); // tiles 5,6
            ldsm4(bA,         bh0, bh1, bh2, bh3);
            ldsm4(bA + 18432, bl0, bl1, bl2, bl3);
            MMA(acc[0], ah0, ah1, ah2, ah3, bh0, bh1);
            MMA(acc[0], ah0, ah1, ah2, ah3, bl0, bl1);
            MMA(acc[0], al0, al1, al2, al3, bh0, bh1);
            MMA(acc[1], ah0, ah1, ah2, ah3, bh2, bh3);
            MMA(acc[1], ah0, ah1, ah2, ah3, bl2, bl3);
            MMA(acc[1], al0, al1, al2, al3, bh2, bh3);
            bA += 2u * 2048u;                                // tiles 7,8
            ldsm4(bA,         bh0, bh1, bh2, bh3);
            ldsm4(bA + 18432, bl0, bl1, bl2, bl3);
            MMA(acc[2], ah0, ah1, ah2, ah3, bh0, bh1);
            MMA(acc[2], ah0, ah1, ah2, ah3, bl0, bl1);
            MMA(acc[2], al0, al1, al2, al3, bh0, bh1);
            MMA(acc[3], ah0, ah1, ah2, ah3, bh2, bh3);
            MMA(acc[3], ah0, ah1, ah2, ah3, bl2, bl3);
            MMA(acc[3], al0, al1, al2, al3, bh2, bh3);
        }
    }

    // ---- register epilogue: relu + b1, partial Z = A @ W2 -------------------
    const int nOff = 2 * (lane & 3);
    const int r0   = mtile * 16 + (lane >> 2);
    const int ntB  = half ? 5 : 0;
    const int ntC  = half ? 4 : 5;
    float z0[10], z1[10];
#pragma unroll
    for (int c = 0; c < 10; ++c) { z0[c] = 0.f; z1[c] = 0.f; }
#pragma unroll
    for (int ti = 0; ti < 5; ++ti) {
        if (ti < ntC) {
            int n = (ntB + ti) * 8 + nOff;
            float a00 = fmaxf(acc[ti][0] + b1s[n],     0.0f);
            float a01 = fmaxf(acc[ti][1] + b1s[n + 1], 0.0f);
            float a10 = fmaxf(acc[ti][2] + b1s[n],     0.0f);
            float a11 = fmaxf(acc[ti][3] + b1s[n + 1], 0.0f);
            const float* w2r0 = W2p + n * 12;
            const float* w2r1 = w2r0 + 12;
#pragma unroll
            for (int c = 0; c < 10; ++c) {
                float wa = w2r0[c], wb = w2r1[c];
                z0[c] = fmaf(a00, wa, fmaf(a01, wb, z0[c]));
                z1[c] = fmaf(a10, wa, fmaf(a11, wb, z1[c]));
            }
        }
    }
#pragma unroll
    for (int off = 1; off <= 2; off <<= 1) {
#pragma unroll
        for (int c = 0; c < 10; ++c) {
            z0[c] += __shfl_xor_sync(0xffffffffu, z0[c], off);
            z1[c] += __shfl_xor_sync(0xffffffffu, z1[c], off);
        }
    }
    __syncthreads();           // all ldmatrix reads of W region done
    if ((lane & 3) == 0) {
#pragma unroll
        for (int c = 0; c < 10; ++c) {
            Zrd[(half * 128 + r0) * 11 + c]     = z0[c];
            Zrd[(half * 128 + r0 + 8) * 11 + c] = z1[c];
        }
    }
    __syncthreads();

    // ---- Z combine + softmax -> S gmem + S^T bf16 hi/lo; others prefetch ---
    float* p1s = (float*)(smc + P1S_B);
    float* p2s = (float*)(smc + P2S_B);
    if (tid < 128) {
        int m = tid;
        const uint32_t mChunk = (uint32_t)((m >> 3) << 4);
        const uint32_t mRem   = (uint32_t)(((m >> 1) & 3) << 2)
                              + (uint32_t)((m & 1) << 1);
        if (m < NPG) {
            float z[10];
#pragma unroll
            for (int c = 0; c < 10; ++c)
                z[c] = Zrd[m * 11 + c] + Zrd[(128 + m) * 11 + c] + b2s[c];
            float mx = z[0];
#pragma unroll
            for (int c = 1; c < 10; ++c) mx = fmaxf(mx, z[c]);
            float ssum = 0.0f;
#pragma unroll
            for (int c = 0; c < 10; ++c) { z[c] = expf(z[c] - mx); ssum += z[c]; }
            float inv = 1.0f / ssum;
            float* gout = out + S_OFF + ((size_t)g * NPG + m) * NC;
#pragma unroll
            for (int c = 0; c < 10; ++c) z[c] *= inv;
#pragma unroll
            for (int c = 0; c < 5; ++c)
                *(float2*)(gout + 2 * c) = make_float2(z[2 * c], z[2 * c + 1]);
#pragma unroll
            for (int c = 0; c < 10; ++c) {
                __nv_bfloat16 shi = __float2bfloat16(z[c]);
                __nv_bfloat16 slo = __float2bfloat16(z[c] - __bfloat162float(shi));
                uint32_t off = (uint32_t)c * 256u
                             + ((mChunk ^ (uint32_t)((c & 7) << 4))) + mRem;
                *(unsigned short*)(smc + STHI_B + off) = __bfloat16_as_ushort(shi);
                *(unsigned short*)(smc + STLO_B + off) = __bfloat16_as_ushort(slo);
            }
        } else {
            // m = 125..127: zero K-pad columns of S^T (all 16 rows)
#pragma unroll
            for (int c = 0; c < 16; ++c) {
                uint32_t off = (uint32_t)c * 256u
                             + ((mChunk ^ (uint32_t)((c & 7) << 4))) + mRem;
                *(unsigned short*)(smc + STHI_B + off) = 0;
                *(unsigned short*)(smc + STLO_B + off) = 0;
            }
        }
    } else {
        int t = tid - 128;
        for (int i = t; i < 1024; i += 384) p1s[i] = __ldg(&p1[i]);
        if (t < 128) p2s[t] = __ldg(&p2[t]);
    }
    __syncthreads();

    // ---- stage E via mma: E = S^T @ H; per-warp 8-column d-tile -------------
    float* Es = (float*)(smc + ES_B);
    {
        const int aRow = ((tA & 1) << 3) + rA;
        const uint32_t aHiBase = sb + STHI_B + (uint32_t)aRow * 256u;
        const int aXor = aRow & 7;
        const int bOff = lane & 15;                    // H row within k-step
        uint32_t bAddr = sb + HHI_B + (uint32_t)bOff * 256u
                       + (uint32_t)((wid ^ (bOff & 7)) << 4);

        float e[4] = {0.f, 0.f, 0.f, 0.f};
#pragma unroll
        for (int s = 0; s < 8; ++s) {
            uint32_t aAddr = aHiBase + (uint32_t)(((2 * s + aCo) ^ aXor) << 4);
            uint32_t sh0, sh1, sh2, sh3, sl0, sl1, sl2, sl3;
            ldsm4(aAddr,        sh0, sh1, sh2, sh3);
            ldsm4(aAddr + 4096, sl0, sl1, sl2, sl3);   // STLO = STHI + 4096
            uint32_t bh0, bh1, bl0, bl1;
            ldsm2t(bAddr,         bh0, bh1);
            ldsm2t(bAddr + 32768, bl0, bl1);           // HLO
            MMA(e, sh0, sh1, sh2, sh3, bh0, bh1);
            MMA(e, sh0, sh1, sh2, sh3, bl0, bl1);
            MMA(e, sl0, sl1, sl2, sl3, bh0, bh1);
            bAddr += 16u * 256u;
        }
        const int c = lane >> 2;
        const int d = 8 * wid + 2 * (lane & 3);
        float* Eout = out + E_OFF + (size_t)g * (NC * D);
        *(float2*)(Es + c * D + d)   = make_float2(e[0], e[1]);
        *(float2*)(Eout + c * D + d) = make_float2(e[0], e[1]);
        if (c + 8 < NC) {
            *(float2*)(Es + (c + 8) * D + d)   = make_float2(e[2], e[3]);
            *(float2*)(Eout + (c + 8) * D + d) = make_float2(e[2], e[3]);
        }
    }
    __syncthreads();

    // ======================= fused downstream ================================
    float* ts    = (float*)(smc + TS_B);
    float* qraw  = (float*)(smc + QR_B);
    float* fms   = (float*)(smc + FMS_B);
    float* red   = (float*)(smc + RED_B);
    float* sc    = (float*)(smc + SC_B);
    float* corrs = (float*)(smc + CORR_B);
    float* cmask = (float*)(smc + CM_B);

    // epoch 1: pred1 partials
    float s0 = 0.f, s1 = 0.f;
#pragma unroll
    for (int r = 0; r < 3; ++r) {
        int i = tid + 512 * r;
        if (i < 1280) {
            float e = Es[i];
            float2 w = __ldg((const float2*)(wf + 2 * i));
            s0 = fmaf(e, w.x, s0);
            s1 = fmaf(e, w.y, s1);
        }
    }
#pragma unroll
    for (int off = 16; off; off >>= 1) {
        s0 += __shfl_down_sync(0xffffffffu, s0, off);
        s1 += __shfl_down_sync(0xffffffffu, s1, off);
    }
    if (lane == 0) { red[wid * 2] = s0; red[wid * 2 + 1] = s1; }
    __syncthreads();

    // epoch 2: sampling | correlation | Q hidden
    if (tid == 0) {
        float z0v = bf[0], z1v = bf[1];
#pragma unroll
        for (int w = 0; w < 16; ++w) { z0v += red[2 * w]; z1v += red[2 * w + 1]; }
        out[P1_OFF + g * 2 + 0] = z0v;
        out[P1_OFF + g * 2 + 1] = z1v;
        float mx = fmaxf(z0v, z1v);
        float e0 = expf(z0v - mx), e1 = expf(z1v - mx);
        float inv = 1.0f / (e0 + e1);
        float pp0 = e0 * inv, pp1 = e1 * inv;

        float u0 = jax_unit_uniform(2u * g);
        float u1 = jax_unit_uniform(2u * g + 1u);
        float l0 = logf(pp0 + 1e-12f) - logf(-logf(u0));
        float l1 = logf(pp1 + 1e-12f) - logf(-logf(u1));
        int sample = (l1 > l0) ? 1 : 0;

        out[IND_OFF + g] = (sample == targets[g]) ? 1.0f : 0.0f;
        sc[0] = pp0 + ((sample == 0) ? (1.0f - pp0) : -pp0);
        sc[1] = pp1 + ((sample == 1) ? (1.0f - pp1) : -pp1);
    }

    if (tid >= 32 && tid < 64) {
        int t = tid - 32;
        int c = t >> 4, f = t & 15;
        float a0 = cis[f], a1 = cis[16 + f];
        float m = fmaxf(a0, a1);
        float e0 = expf(a0 - m), e1 = expf(a1 - m);
        float colv = ((c == 0) ? e0 : e1) / (e0 + e1);
        float rm = -1e30f;
        for (int ff = 0; ff < 16; ++ff) rm = fmaxf(rm, cias[c * 16 + ff]);
        float rs = 0.f;
        for (int ff = 0; ff < 16; ++ff) rs += expf(cias[c * 16 + ff] - rm);
        corrs[c * 16 + f] = colv * (expf(cias[c * 16 + f] - rm) / rs);
    }

    if (tid >= 192) {                // Q hidden, 4-way k-split
        int t  = tid - 192;
        int u  = t >> 2, ks = t & 3;
        int c  = u >> 3, j = u & 7;
        float a = 0.0f;
        const float* ec = Es + c * 128 + 32 * ks;
        const float* pj = p1s + (32 * ks) * 8 + j;
#pragma unroll 8
        for (int k = 0; k < 32; ++k) a = fmaf(ec[k], pj[8 * k], a);
        a += __shfl_down_sync(0xffffffffu, a, 2);
        a += __shfl_down_sync(0xffffffffu, a, 1);
        if (ks == 0) ts[u] = fmaxf(a + pb1s[j], 0.0f);
    }
    __syncthreads();

    // epoch 3: cmask | Q output
    if (tid < 16) cmask[tid] = sc[0] * corrs[tid] + sc[1] * corrs[16 + tid];

    if (tid >= 160 && tid < 320) {
        int t = tid - 160;
        int c = t >> 4, f = t & 15;
        float a = pb2s[f];
#pragma unroll
        for (int j = 0; j < 8; ++j) a = fmaf(ts[c * 8 + j], p2s[j * 16 + f], a);
        qraw[t] = a;
    }
    __syncthreads();

    // epoch 4: Q softmax + feature mask
    if (tid < 160) {
        int c = tid >> 4, f = tid & 15;
        float v = qraw[tid];
        float mx = v;
#pragma unroll
        for (int off = 8; off; off >>= 1)
            mx = fmaxf(mx, __shfl_xor_sync(0xffffffffu, mx, off));
        float e = expf(v - mx);
        float ssum = e;
#pragma unroll
        for (int off = 8; off; off >>= 1)
            ssum += __shfl_xor_sync(0xffffffffu, ssum, off);
        float q = e / ssum;
        out[Q_OFF + (size_t)g * 160 + c * 16 + f] = q;
        float fm = q * cmask[f];
#pragma unroll
        for (int off = 8; off; off >>= 1)
            fm += __shfl_xor_sync(0xffffffffu, fm, off);
        if (f == 0) fms[c] = fm;
    }
    __syncthreads();

    // epoch 5: pred2
    s0 = 0.f; s1 = 0.f;
#pragma unroll
    for (int r = 0; r < 3; ++r) {
        int i = tid + 512 * r;
        if (i < 1280) {
            float e = fms[i >> 7] * Es[i];
            float2 w = __ldg((const float2*)(wf + 2 * i));
            s0 = fmaf(e, w.x, s0);
            s1 = fmaf(e, w.y, s1);
        }
    }
#pragma unroll
    for (int off = 16; off; off >>= 1) {
        s0 += __shfl_down_sync(0xffffffffu, s0, off);
        s1 += __shfl_down_sync(0xffffffffu, s1, off);
    }
    if (lane == 0) { red[wid * 2] = s0; red[wid * 2 + 1] = s1; }
    __syncthreads();
    if (tid == 0) {
        float z0v = bf[0], z1v = bf[1];
#pragma unroll
        for (int w = 0; w < 16; ++w) { z0v += red[2 * w]; z1v += red[2 * w + 1]; }
        out[P2_OFF + g * 2 + 0] = z0v;
        out[P2_OFF + g * 2 + 1] = z1v;
    }
}

// ---------------------------------------------------------------------------
extern "C" void kernel_launch(void* const* d_in, const int* in_sizes, int n_in,
                              void* d_out, int out_size)
{
    const float* H   = (const float*)d_in[0];
    const int*   tgt = (const int*)  d_in[2];
    const float* w1  = (const float*)d_in[3];
    const float* b1  = (const float*)d_in[4];
    const float* w2  = (const float*)d_in[5];
    const float* b2  = (const float*)d_in[6];
    const float* wf  = (const float*)d_in[7];
    const float* bf  = (const float*)d_in[8];
    const float* p1  = (const float*)d_in[9];
    const float* pb1 = (const float*)d_in[10];
    const float* p2  = (const float*)d_in[11];
    const float* pb2 = (const float*)d_in[12];
    const float* ci  = (const float*)d_in[13];
    const float* cia = (const float*)d_in[14];
    float* out = (float*)d_out;

    static bool attr_set = false;
    if (!attr_set) {
        cudaFuncSetAttribute(ciflow_fused,
                             cudaFuncAttributeMaxDynamicSharedMemorySize, SMEM_TOTAL);
        attr_set = true;
    }

    ciflow_prep<<<18, 256>>>(w1, w2, b1);
    ciflow_fused<<<NGRAPH, 512, SMEM_TOTAL>>>(H, tgt, b2, wf, bf,
                                              p1, pb1, p2, pb2, ci, cia, out);
}